// round 4
// baseline (speedup 1.0000x reference)
#include <cuda_runtime.h>
#include <cstdint>

#define BB   16
#define C_IN 256
#define CRr  128
#define KKGc 144
#define HWn  3136
#define HH   56
#define WWc  56

typedef unsigned long long ull;

// ---------------- scratch (allocation-free: __device__ globals) ----------------
__device__ float g_t[(size_t)BB * CRr * HWn];     // reduce-conv output  [b][cr][hw]
__device__ float g_kern[(size_t)BB * KKGc * HWn]; // span-conv output    [b][o][hw]
__device__ float g_scale[CRr];
__device__ float g_shift[CRr];

// ---------------- packed fp32x2 helpers ----------------
__device__ __forceinline__ ull dup2(float x) {
    ull r;
    asm("mov.b64 %0, {%1, %1};" : "=l"(r) : "f"(x));
    return r;
}
__device__ __forceinline__ void fma2(ull& acc, ull a, ull b) {
    asm("fma.rn.f32x2 %0, %1, %2, %0;" : "+l"(acc) : "l"(a), "l"(b));
}
__device__ __forceinline__ void unpack2(ull v, float& lo, float& hi) {
    asm("mov.b64 {%0, %1}, %2;" : "=f"(lo), "=f"(hi) : "l"(v));
}

// ---------------------------------------------------------------------------
// Tiled fp32 GEMM (f32x2-packed, M-paired accumulators, B pre-duplicated in
// smem, double-buffered single-sync pipeline). Per batch z:
//   C[m][n] = sum_k A[m][k] * Bin[k][n] + bias[m]
// SPAN=true : Bin = relu(g_t * scale + shift), Cout = g_kern   (K=128, M=144)
// SPAN=false: Bin = X,                         Cout = g_t      (K=256, M=128)
// ---------------------------------------------------------------------------
template<int M, int K, bool SPAN>
__global__ __launch_bounds__(256)
void gemm_k(const float* __restrict__ A,
            const float* __restrict__ bias,
            const float* __restrict__ X)
{
    constexpr int BM = 128, BN = 128, BK = 16, TM = 8, TN = 8;
    __shared__ __align__(16) float As[2][BK][BM + 4];
    __shared__ __align__(16) ull   Bs[2][BK][BN];   // each entry = {v, v}

    const int b   = blockIdx.z;
    const int n0  = blockIdx.x * BN;
    const int m0  = blockIdx.y * BM;
    const int tid = threadIdx.x;
    const int tx  = tid & 15;   // N dim (8 cols)
    const int ty  = tid >> 4;   // M dim (4 m-pairs)

    const float* Bin  = SPAN ? (g_t    + (size_t)b * K * HWn) : (X   + (size_t)b * K * HWn);
    float*       Cout = SPAN ? (g_kern + (size_t)b * M * HWn) : (g_t + (size_t)b * M * HWn);

    // warp-aligned skip for the partial M block (M=144: block y=1 -> 16 live rows)
    bool active = true;
    if constexpr (M % BM != 0) active = (m0 + ty * TM) < M;

    ull acc2[TM / 2][TN] = {};   // [m-pair][n], packed {row m, row m+1}

    // ---- global->reg load lambdas (manually inlined as macel) ----
    const int arow = tid >> 1;          // 0..127 (m within tile)
    const int ak   = (tid & 1) * 8;     // 0 or 8 (k offset)

    float  aReg[8];
    float4 bReg[2];
    int    bCol[2], bRow[2];

    auto loadA = [&](int k0) {
        const int grow = m0 + arow;
        bool ok = true;
        if constexpr (M % BM != 0) ok = (grow < M);
        if (ok) {
            const float* ap = A + (size_t)grow * K + k0 + ak;
            float4 v0 = *reinterpret_cast<const float4*>(ap);
            float4 v1 = *reinterpret_cast<const float4*>(ap + 4);
            aReg[0]=v0.x; aReg[1]=v0.y; aReg[2]=v0.z; aReg[3]=v0.w;
            aReg[4]=v1.x; aReg[5]=v1.y; aReg[6]=v1.z; aReg[7]=v1.w;
        } else {
            #pragma unroll
            for (int i = 0; i < 8; i++) aReg[i] = 0.f;
        }
    };
    auto loadB = [&](int k0) {
        #pragma unroll
        for (int it = 0; it < 2; it++) {
            const int lin  = tid + it * 256;
            bRow[it] = lin >> 5;            // 0..15
            const int bc4  = lin & 31;      // 0..31
            bCol[it] = bc4 * 4;
            const int col  = n0 + bc4 * 4;
            float4 v;
            if (col < HWn) {
                v = *reinterpret_cast<const float4*>(Bin + (size_t)(k0 + bRow[it]) * HWn + col);
                if constexpr (SPAN) {
                    const int c   = k0 + bRow[it];
                    const float sc = g_scale[c], sh = g_shift[c];
                    v.x = fmaxf(fmaf(v.x, sc, sh), 0.f);
                    v.y = fmaxf(fmaf(v.y, sc, sh), 0.f);
                    v.z = fmaxf(fmaf(v.z, sc, sh), 0.f);
                    v.w = fmaxf(fmaf(v.w, sc, sh), 0.f);
                }
            } else {
                v = make_float4(0.f, 0.f, 0.f, 0.f);
            }
            bReg[it] = v;
        }
    };
    auto storeTile = [&](int buf) {
        As[buf][ak + 0][arow] = aReg[0]; As[buf][ak + 1][arow] = aReg[1];
        As[buf][ak + 2][arow] = aReg[2]; As[buf][ak + 3][arow] = aReg[3];
        As[buf][ak + 4][arow] = aReg[4]; As[buf][ak + 5][arow] = aReg[5];
        As[buf][ak + 6][arow] = aReg[6]; As[buf][ak + 7][arow] = aReg[7];
        #pragma unroll
        for (int it = 0; it < 2; it++) {
            ull* bp = &Bs[buf][bRow[it]][bCol[it]];
            bp[0] = dup2(bReg[it].x);
            bp[1] = dup2(bReg[it].y);
            bp[2] = dup2(bReg[it].z);
            bp[3] = dup2(bReg[it].w);
        }
    };

    // ---- prologue: tile 0 ----
    loadA(0); loadB(0);
    storeTile(0);
    __syncthreads();

    int buf = 0;
    for (int k0 = 0; k0 < K; k0 += BK) {
        const bool more = (k0 + BK) < K;
        if (more) { loadA(k0 + BK); loadB(k0 + BK); }

        if (active) {
            #pragma unroll
            for (int k = 0; k < BK; k++) {
                // A m-pairs: 4 x 64-bit packed {m, m+1} straight from smem
                const ulonglong2* ap =
                    reinterpret_cast<const ulonglong2*>(&As[buf][k][ty * TM]);
                ulonglong2 a01 = ap[0], a23 = ap[1];
                ull a2[4] = { a01.x, a01.y, a23.x, a23.y };
                // B duplicated pairs: 8 x {b, b}
                const ulonglong2* bp =
                    reinterpret_cast<const ulonglong2*>(&Bs[buf][k][tx * TN]);
                ulonglong2 b01 = bp[0], b23 = bp[1], b45 = bp[2], b67 = bp[3];
                ull b2[8] = { b01.x, b01.y, b23.x, b23.y, b45.x, b45.y, b67.x, b67.y };
                #pragma unroll
                for (int i = 0; i < TM / 2; i++)
                    #pragma unroll
                    for (int j = 0; j < TN; j++)
                        fma2(acc2[i][j], a2[i], b2[j]);
            }
        }

        if (more) {
            storeTile(buf ^ 1);
            __syncthreads();
            buf ^= 1;
        }
    }

    // ---- store (+bias) ----
    const int colb = n0 + tx * TN;
    if (active && colb < HWn) {
        #pragma unroll
        for (int i = 0; i < TM / 2; i++) {
            float lo[TN], hi[TN];
            #pragma unroll
            for (int j = 0; j < TN; j++) unpack2(acc2[i][j], lo[j], hi[j]);
            #pragma unroll
            for (int half = 0; half < 2; half++) {
                const int grow = m0 + ty * TM + 2 * i + half;
                bool ok = true;
                if constexpr (M % BM != 0) ok = (grow < M);
                if (ok) {
                    const float* src = half ? hi : lo;
                    const float bv = bias[grow];
                    float4 o0, o1;
                    o0.x = src[0] + bv; o0.y = src[1] + bv;
                    o0.z = src[2] + bv; o0.w = src[3] + bv;
                    o1.x = src[4] + bv; o1.y = src[5] + bv;
                    o1.z = src[6] + bv; o1.w = src[7] + bv;
                    float* cp = Cout + (size_t)grow * HWn + colb;
                    *reinterpret_cast<float4*>(cp)     = o0;
                    *reinterpret_cast<float4*>(cp + 4) = o1;
                }
            }
        }
    }
}

// ---------------------------------------------------------------------------
// BatchNorm statistics (deterministic fixed-order tree reduction).
// ---------------------------------------------------------------------------
__global__ __launch_bounds__(1024)
void bn_stats(const float* __restrict__ gamma, const float* __restrict__ beta)
{
    const int c   = blockIdx.x;
    const int tid = threadIdx.x;
    float s = 0.f, sq = 0.f;
    for (int b = 0; b < BB; b++) {
        const float* p = g_t + ((size_t)b * CRr + c) * HWn;
        for (int i = tid; i < HWn; i += 1024) {
            float v = p[i];
            s  += v;
            sq  = fmaf(v, v, sq);
        }
    }
    __shared__ float ss[1024], sqs[1024];
    ss[tid] = s; sqs[tid] = sq;
    __syncthreads();
    for (int o = 512; o > 0; o >>= 1) {
        if (tid < o) { ss[tid] += ss[tid + o]; sqs[tid] += sqs[tid + o]; }
        __syncthreads();
    }
    if (tid == 0) {
        const float inv  = 1.f / (float)(BB * HWn);
        const float mean = ss[0] * inv;
        const float var  = sqs[0] * inv - mean * mean;
        const float rstd = rsqrtf(var + 1e-5f);
        const float sc   = gamma[c] * rstd;
        g_scale[c] = sc;
        g_shift[c] = beta[c] - mean * sc;
    }
}

// ---------------------------------------------------------------------------
// Involution gather, d-pair packed (f32x2). x tile staged d-innermost so a
// d-pair is one 8-byte LDS; taps duplicated once into registers.
//   out[b, g*16+d, h, w] = sum_{i,j} x[b, g*16+d, h+i-1, w+j-1]
//                              * kern[b, (i*3+j)*16+g, h, w]
// ---------------------------------------------------------------------------
#define THT 4
#define DPAD 18   // 16 d + pad 2: keeps pairs 8B-aligned, 2-way conflicts max
__global__ __launch_bounds__(224)
void involution_kernel(const float* __restrict__ x, float* __restrict__ out)
{
    __shared__ __align__(16) float sx[THT + 2][60][DPAD]; // [row][col(halo)][d]
    __shared__ float skn[9][THT][WWc];

    const int h0  = blockIdx.x * THT;
    const int g   = blockIdx.y;
    const int b   = blockIdx.z;
    const int tid = threadIdx.x;            // 0..223

    // ---- stage x tile transposed: d innermost ----
    const float* xg = x + ((size_t)b * C_IN + g * 16) * HWn;
    for (int idx = tid; idx < 16 * (THT + 2) * 58; idx += 224) {
        const int d    = idx / ((THT + 2) * 58);
        const int rem  = idx - d * ((THT + 2) * 58);
        const int r    = rem / 58;
        const int cpos = rem - r * 58;
        const int hh   = h0 - 1 + r;
        const int ww   = cpos - 1;
        float v = 0.f;
        if (hh >= 0 && hh < HH && ww >= 0 && ww < WWc)
            v = xg[(size_t)d * HWn + hh * WWc + ww];
        sx[r][cpos][d] = v;
    }
    // ---- stage kernel slice: 9 taps x THT rows x 56 ----
    const float* kg = g_kern + ((size_t)b * KKGc + g) * HWn + h0 * WWc;
    for (int idx = tid; idx < 9 * THT * WWc; idx += 224) {
        const int t  = idx / (THT * WWc);
        const int r  = (idx / WWc) % THT;
        const int ww = idx % WWc;
        skn[t][r][ww] = kg[(size_t)t * 16 * HWn + r * WWc + ww];
    }
    __syncthreads();

    const int w  = tid % WWc;
    const int hl = tid / WWc;   // 0..3

    ull kv2[9];
    #pragma unroll
    for (int t = 0; t < 9; t++) kv2[t] = dup2(skn[t][hl][w]);

    const float* sbase = &sx[hl][w][0];
    float* og = out + ((size_t)b * C_IN + g * 16) * HWn + (h0 + hl) * WWc + w;

    #pragma unroll
    for (int dp = 0; dp < 8; dp++) {
        ull acc = 0;
        #pragma unroll
        for (int i = 0; i < 3; i++)
            #pragma unroll
            for (int j = 0; j < 3; j++) {
                const ull xv = *reinterpret_cast<const ull*>(
                    sbase + ((i * 60 + j) * DPAD + 2 * dp));
                fma2(acc, xv, kv2[i * 3 + j]);
            }
        float lo, hi;
        unpack2(acc, lo, hi);
        og[(size_t)(2 * dp)     * HWn] = lo;
        og[(size_t)(2 * dp + 1) * HWn] = hi;
    }
}

// ---------------------------------------------------------------------------
extern "C" void kernel_launch(void* const* d_in, const int* in_sizes, int n_in,
                              void* d_out, int out_size)
{
    (void)in_sizes; (void)n_in; (void)out_size;
    const float* x        = (const float*)d_in[0];
    const float* w_reduce = (const float*)d_in[1];
    const float* b_reduce = (const float*)d_in[2];
    const float* gamma    = (const float*)d_in[3];
    const float* beta     = (const float*)d_in[4];
    const float* w_span   = (const float*)d_in[5];
    const float* b_span   = (const float*)d_in[6];
    float* out = (float*)d_out;

    // 1) reduce conv:  t = w_reduce @ x + b_reduce
    dim3 g1((HWn + 127) / 128, 1, BB);
    gemm_k<CRr, C_IN, false><<<g1, 256>>>(w_reduce, b_reduce, x);

    // 2) BN batch statistics -> folded scale/shift
    bn_stats<<<CRr, 1024>>>(gamma, beta);

    // 3) span conv with fused BN+ReLU: kern = w_span @ relu(bn(t)) + b_span
    dim3 g2((HWn + 127) / 128, (KKGc + 127) / 128, BB);
    gemm_k<KKGc, CRr, true><<<g2, 256>>>(w_span, b_span, nullptr);

    // 4) involution gather
    dim3 g3(HH / THT, 16, BB);
    involution_kernel<<<g3, 224>>>(x, out);
}

// round 5
// speedup vs baseline: 1.0011x; 1.0011x over previous
#include <cuda_runtime.h>
#include <cstdint>

#define BB   16
#define C_IN 256
#define CRr  128
#define KKGc 144
#define HWn  3136
#define HH   56
#define WWc  56

typedef unsigned long long ull;

// ---------------- scratch (allocation-free: __device__ globals) ----------------
__device__ float g_t[(size_t)BB * CRr * HWn];     // reduce-conv output  [b][cr][hw]
__device__ float g_kern[(size_t)BB * KKGc * HWn]; // span-conv output    [b][o][hw]
__device__ float g_scale[CRr];
__device__ float g_shift[CRr];

// ---------------- packed fp32x2 helpers ----------------
__device__ __forceinline__ ull dup2(float x) {
    ull r;
    asm("mov.b64 %0, {%1, %1};" : "=l"(r) : "f"(x));
    return r;
}
__device__ __forceinline__ void fma2(ull& acc, ull a, ull b) {
    asm("fma.rn.f32x2 %0, %1, %2, %0;" : "+l"(acc) : "l"(a), "l"(b));
}
__device__ __forceinline__ void unpack2(ull v, float& lo, float& hi) {
    asm("mov.b64 {%0, %1}, %2;" : "=f"(lo), "=f"(hi) : "l"(v));
}

// ---------------------------------------------------------------------------
// Tiled fp32 GEMM (f32x2-packed, M-paired accumulators, B pre-duplicated in
// smem, double-buffered single-sync pipeline). Per batch z:
//   C[m][n] = sum_k A[m][k] * Bin[k][n] + bias[m]
// SPAN=true : Bin = relu(g_t * scale + shift), Cout = g_kern   (K=128, M=144)
// SPAN=false: Bin = X,                         Cout = g_t      (K=256, M=128)
// ---------------------------------------------------------------------------
template<int M, int K, bool SPAN>
__global__ __launch_bounds__(256)
void gemm_k(const float* __restrict__ A,
            const float* __restrict__ bias,
            const float* __restrict__ X)
{
    constexpr int BM = 128, BN = 128, BK = 16, TM = 8, TN = 8;
    __shared__ __align__(16) float As[2][BK][BM + 4];
    __shared__ __align__(16) ull   Bs[2][BK][BN];   // each entry = {v, v}

    const int b   = blockIdx.z;
    const int n0  = blockIdx.x * BN;
    const int m0  = blockIdx.y * BM;
    const int tid = threadIdx.x;
    const int tx  = tid & 15;   // N dim (8 cols)
    const int ty  = tid >> 4;   // M dim (4 m-pairs)

    const float* Bin  = SPAN ? (g_t    + (size_t)b * K * HWn) : (X   + (size_t)b * K * HWn);
    float*       Cout = SPAN ? (g_kern + (size_t)b * M * HWn) : (g_t + (size_t)b * M * HWn);

    // warp-aligned skip for the partial M block (M=144: block y=1 -> 16 live rows)
    bool active = true;
    if constexpr (M % BM != 0) active = (m0 + ty * TM) < M;

    ull acc2[TM / 2][TN] = {};   // [m-pair][n], packed {row m, row m+1}

    // ---- global->reg load lambdas (manually inlined as macel) ----
    const int arow = tid >> 1;          // 0..127 (m within tile)
    const int ak   = (tid & 1) * 8;     // 0 or 8 (k offset)

    float  aReg[8];
    float4 bReg[2];
    int    bCol[2], bRow[2];

    auto loadA = [&](int k0) {
        const int grow = m0 + arow;
        bool ok = true;
        if constexpr (M % BM != 0) ok = (grow < M);
        if (ok) {
            const float* ap = A + (size_t)grow * K + k0 + ak;
            float4 v0 = *reinterpret_cast<const float4*>(ap);
            float4 v1 = *reinterpret_cast<const float4*>(ap + 4);
            aReg[0]=v0.x; aReg[1]=v0.y; aReg[2]=v0.z; aReg[3]=v0.w;
            aReg[4]=v1.x; aReg[5]=v1.y; aReg[6]=v1.z; aReg[7]=v1.w;
        } else {
            #pragma unroll
            for (int i = 0; i < 8; i++) aReg[i] = 0.f;
        }
    };
    auto loadB = [&](int k0) {
        #pragma unroll
        for (int it = 0; it < 2; it++) {
            const int lin  = tid + it * 256;
            bRow[it] = lin >> 5;            // 0..15
            const int bc4  = lin & 31;      // 0..31
            bCol[it] = bc4 * 4;
            const int col  = n0 + bc4 * 4;
            float4 v;
            if (col < HWn) {
                v = *reinterpret_cast<const float4*>(Bin + (size_t)(k0 + bRow[it]) * HWn + col);
                if constexpr (SPAN) {
                    const int c   = k0 + bRow[it];
                    const float sc = g_scale[c], sh = g_shift[c];
                    v.x = fmaxf(fmaf(v.x, sc, sh), 0.f);
                    v.y = fmaxf(fmaf(v.y, sc, sh), 0.f);
                    v.z = fmaxf(fmaf(v.z, sc, sh), 0.f);
                    v.w = fmaxf(fmaf(v.w, sc, sh), 0.f);
                }
            } else {
                v = make_float4(0.f, 0.f, 0.f, 0.f);
            }
            bReg[it] = v;
        }
    };
    auto storeTile = [&](int buf) {
        As[buf][ak + 0][arow] = aReg[0]; As[buf][ak + 1][arow] = aReg[1];
        As[buf][ak + 2][arow] = aReg[2]; As[buf][ak + 3][arow] = aReg[3];
        As[buf][ak + 4][arow] = aReg[4]; As[buf][ak + 5][arow] = aReg[5];
        As[buf][ak + 6][arow] = aReg[6]; As[buf][ak + 7][arow] = aReg[7];
        #pragma unroll
        for (int it = 0; it < 2; it++) {
            ull* bp = &Bs[buf][bRow[it]][bCol[it]];
            bp[0] = dup2(bReg[it].x);
            bp[1] = dup2(bReg[it].y);
            bp[2] = dup2(bReg[it].z);
            bp[3] = dup2(bReg[it].w);
        }
    };

    // ---- prologue: tile 0 ----
    loadA(0); loadB(0);
    storeTile(0);
    __syncthreads();

    int buf = 0;
    for (int k0 = 0; k0 < K; k0 += BK) {
        const bool more = (k0 + BK) < K;
        if (more) { loadA(k0 + BK); loadB(k0 + BK); }

        if (active) {
            #pragma unroll
            for (int k = 0; k < BK; k++) {
                // A m-pairs: 4 x 64-bit packed {m, m+1} straight from smem
                const ulonglong2* ap =
                    reinterpret_cast<const ulonglong2*>(&As[buf][k][ty * TM]);
                ulonglong2 a01 = ap[0], a23 = ap[1];
                ull a2[4] = { a01.x, a01.y, a23.x, a23.y };
                // B duplicated pairs: 8 x {b, b}
                const ulonglong2* bp =
                    reinterpret_cast<const ulonglong2*>(&Bs[buf][k][tx * TN]);
                ulonglong2 b01 = bp[0], b23 = bp[1], b45 = bp[2], b67 = bp[3];
                ull b2[8] = { b01.x, b01.y, b23.x, b23.y, b45.x, b45.y, b67.x, b67.y };
                #pragma unroll
                for (int i = 0; i < TM / 2; i++)
                    #pragma unroll
                    for (int j = 0; j < TN; j++)
                        fma2(acc2[i][j], a2[i], b2[j]);
            }
        }

        if (more) {
            storeTile(buf ^ 1);
            __syncthreads();
            buf ^= 1;
        }
    }

    // ---- store (+bias) ----
    const int colb = n0 + tx * TN;
    if (active && colb < HWn) {
        #pragma unroll
        for (int i = 0; i < TM / 2; i++) {
            float lo[TN], hi[TN];
            #pragma unroll
            for (int j = 0; j < TN; j++) unpack2(acc2[i][j], lo[j], hi[j]);
            #pragma unroll
            for (int half = 0; half < 2; half++) {
                const int grow = m0 + ty * TM + 2 * i + half;
                bool ok = true;
                if constexpr (M % BM != 0) ok = (grow < M);
                if (ok) {
                    const float* src = half ? hi : lo;
                    const float bv = bias[grow];
                    float4 o0, o1;
                    o0.x = src[0] + bv; o0.y = src[1] + bv;
                    o0.z = src[2] + bv; o0.w = src[3] + bv;
                    o1.x = src[4] + bv; o1.y = src[5] + bv;
                    o1.z = src[6] + bv; o1.w = src[7] + bv;
                    float* cp = Cout + (size_t)grow * HWn + colb;
                    *reinterpret_cast<float4*>(cp)     = o0;
                    *reinterpret_cast<float4*>(cp + 4) = o1;
                }
            }
        }
    }
}

// ---------------------------------------------------------------------------
// BatchNorm statistics (deterministic fixed-order tree reduction).
// ---------------------------------------------------------------------------
__global__ __launch_bounds__(1024)
void bn_stats(const float* __restrict__ gamma, const float* __restrict__ beta)
{
    const int c   = blockIdx.x;
    const int tid = threadIdx.x;
    float s = 0.f, sq = 0.f;
    for (int b = 0; b < BB; b++) {
        const float* p = g_t + ((size_t)b * CRr + c) * HWn;
        for (int i = tid; i < HWn; i += 1024) {
            float v = p[i];
            s  += v;
            sq  = fmaf(v, v, sq);
        }
    }
    __shared__ float ss[1024], sqs[1024];
    ss[tid] = s; sqs[tid] = sq;
    __syncthreads();
    for (int o = 512; o > 0; o >>= 1) {
        if (tid < o) { ss[tid] += ss[tid + o]; sqs[tid] += sqs[tid + o]; }
        __syncthreads();
    }
    if (tid == 0) {
        const float inv  = 1.f / (float)(BB * HWn);
        const float mean = ss[0] * inv;
        const float var  = sqs[0] * inv - mean * mean;
        const float rstd = rsqrtf(var + 1e-5f);
        const float sc   = gamma[c] * rstd;
        g_scale[c] = sc;
        g_shift[c] = beta[c] - mean * sc;
    }
}

// ---------------------------------------------------------------------------
// Involution gather, d-pair packed (f32x2). x tile staged d-innermost so a
// d-pair is one 8-byte LDS; taps duplicated once into registers.
//   out[b, g*16+d, h, w] = sum_{i,j} x[b, g*16+d, h+i-1, w+j-1]
//                              * kern[b, (i*3+j)*16+g, h, w]
// ---------------------------------------------------------------------------
#define THT 4
#define DPAD 18   // 16 d + pad 2: keeps pairs 8B-aligned, 2-way conflicts max
__global__ __launch_bounds__(224)
void involution_kernel(const float* __restrict__ x, float* __restrict__ out)
{
    __shared__ __align__(16) float sx[THT + 2][60][DPAD]; // [row][col(halo)][d]
    __shared__ float skn[9][THT][WWc];

    const int h0  = blockIdx.x * THT;
    const int g   = blockIdx.y;
    const int b   = blockIdx.z;
    const int tid = threadIdx.x;            // 0..223

    // ---- stage x tile transposed: d innermost ----
    const float* xg = x + ((size_t)b * C_IN + g * 16) * HWn;
    for (int idx = tid; idx < 16 * (THT + 2) * 58; idx += 224) {
        const int d    = idx / ((THT + 2) * 58);
        const int rem  = idx - d * ((THT + 2) * 58);
        const int r    = rem / 58;
        const int cpos = rem - r * 58;
        const int hh   = h0 - 1 + r;
        const int ww   = cpos - 1;
        float v = 0.f;
        if (hh >= 0 && hh < HH && ww >= 0 && ww < WWc)
            v = xg[(size_t)d * HWn + hh * WWc + ww];
        sx[r][cpos][d] = v;
    }
    // ---- stage kernel slice: 9 taps x THT rows x 56 ----
    const float* kg = g_kern + ((size_t)b * KKGc + g) * HWn + h0 * WWc;
    for (int idx = tid; idx < 9 * THT * WWc; idx += 224) {
        const int t  = idx / (THT * WWc);
        const int r  = (idx / WWc) % THT;
        const int ww = idx % WWc;
        skn[t][r][ww] = kg[(size_t)t * 16 * HWn + r * WWc + ww];
    }
    __syncthreads();

    const int w  = tid % WWc;
    const int hl = tid / WWc;   // 0..3

    ull kv2[9];
    #pragma unroll
    for (int t = 0; t < 9; t++) kv2[t] = dup2(skn[t][hl][w]);

    const float* sbase = &sx[hl][w][0];
    float* og = out + ((size_t)b * C_IN + g * 16) * HWn + (h0 + hl) * WWc + w;

    #pragma unroll
    for (int dp = 0; dp < 8; dp++) {
        ull acc = 0;
        #pragma unroll
        for (int i = 0; i < 3; i++)
            #pragma unroll
            for (int j = 0; j < 3; j++) {
                const ull xv = *reinterpret_cast<const ull*>(
                    sbase + ((i * 60 + j) * DPAD + 2 * dp));
                fma2(acc, xv, kv2[i * 3 + j]);
            }
        float lo, hi;
        unpack2(acc, lo, hi);
        og[(size_t)(2 * dp)     * HWn] = lo;
        og[(size_t)(2 * dp + 1) * HWn] = hi;
    }
}

// ---------------------------------------------------------------------------
extern "C" void kernel_launch(void* const* d_in, const int* in_sizes, int n_in,
                              void* d_out, int out_size)
{
    (void)in_sizes; (void)n_in; (void)out_size;
    const float* x        = (const float*)d_in[0];
    const float* w_reduce = (const float*)d_in[1];
    const float* b_reduce = (const float*)d_in[2];
    const float* gamma    = (const float*)d_in[3];
    const float* beta     = (const float*)d_in[4];
    const float* w_span   = (const float*)d_in[5];
    const float* b_span   = (const float*)d_in[6];
    float* out = (float*)d_out;

    // 1) reduce conv:  t = w_reduce @ x + b_reduce
    dim3 g1((HWn + 127) / 128, 1, BB);
    gemm_k<CRr, C_IN, false><<<g1, 256>>>(w_reduce, b_reduce, x);

    // 2) BN batch statistics -> folded scale/shift
    bn_stats<<<CRr, 1024>>>(gamma, beta);

    // 3) span conv with fused BN+ReLU: kern = w_span @ relu(bn(t)) + b_span
    dim3 g2((HWn + 127) / 128, (KKGc + 127) / 128, BB);
    gemm_k<KKGc, CRr, true><<<g2, 256>>>(w_span, b_span, nullptr);

    // 4) involution gather
    dim3 g3(HH / THT, 16, BB);
    involution_kernel<<<g3, 224>>>(x, out);
}